// round 12
// baseline (speedup 1.0000x reference)
#include <cuda_runtime.h>

#define S_TILE   16
#define KF       32
#define ROWS     48            // S_TILE + KF (ring buffer size)
#define CHAIN    4             // s-tiles per CTA
#define DCONST   1024
#define D4       256           // D / 4
#define PITCH4   257           // float4 pitch per row
#define COLS     48
#define WPITCH   50            // weight-row pitch in u64 (even -> 16B aligned)
#define NEG_BIG  -1.0e9f

// weight row r at WROW(r) u64; +2 stagger per 8 rows keeps pairs bank-clean
#define WROW(r)  ((r) * WPITCH + (((r) >> 3) << 1))
#define W_U64    800

#define TILE_F4      (ROWS * PITCH4)          // 12336 f4
#define RED_OFF      (TILE_F4 * 4)            // 49344 floats
#define RED_SIZE     (4 * S_TILE * COLS)      // 3072 floats (4 d-groups)
#define W_OFF        (RED_OFF + RED_SIZE)     // 52416 (byte 209664: 16B aligned)
#define SMEM_FLOATS  (W_OFF + 2 * W_U64 * 2)  // two weight buffers
#define SMEM_BYTES   (SMEM_FLOATS * 4)        // 222464 B

typedef unsigned long long u64;

__device__ __forceinline__ void fma2(u64& d, u64 a, u64 b) {
    asm("fma.rn.f32x2 %0, %1, %2, %0;" : "+l"(d) : "l"(a), "l"(b));
}
__device__ __forceinline__ float sum2(u64 a) {
    float2 v = *reinterpret_cast<float2*>(&a);
    return v.x + v.y;
}

__global__ __launch_bounds__(512, 1)
void future_encoder_kernel(const float* __restrict__ in,
                           float* __restrict__ out,
                           int S)
{
    extern __shared__ float smem[];
    ulonglong2* tileU = reinterpret_cast<ulonglong2*>(smem);
    float4*     tile4 = reinterpret_cast<float4*>(smem);
    float*      red   = smem + RED_OFF;
    u64*        Wd    = reinterpret_cast<u64*>(smem + W_OFF);

    const int tid   = threadIdx.x;
    const int chain = blockIdx.x;
    const int bb    = blockIdx.y;
    const int t0    = chain * CHAIN;

    const float4* in4  = reinterpret_cast<const float4*>(in)  + (size_t)bb * S * D4;
    float4*       out4 = reinterpret_cast<float4*>(out)       + (size_t)bb * S * D4;

    // ---- initial load: 48 rows into slots 0..47 ----
    {
        const int half = tid >> 8;
        const int col  = tid & 255;
        #pragma unroll 4
        for (int it2 = 0; it2 < 24; ++it2) {
            const int r = it2 * 2 + half;
            int gr = t0 * S_TILE + r;
            if (gr > S - 1) gr = S - 1;
            tile4[r * PITCH4 + col] = in4[(size_t)gr * D4 + col];
        }
    }

    float4 st[8];   // refresh stash (rows split: X krow 0-7, Y krow 8-15)

    #pragma unroll 1
    for (int it = 0; it <= CHAIN; ++it) {
        __syncthreads();   // ring + weight buffers consistent

        const int rotI = (it * S_TILE) % ROWS;                       // tile it base slot
        const int rotP = (it >= 1) ? ((it - 1) * S_TILE) % ROWS : 0; // tile it-1 base slot
        const int bufC = it & 1;          // weight buffer written this iter (tile it)
        const int bufP = bufC ^ 1;        // weight buffer read by Y (tile it-1)

        if (tid < 256) {
            // ================= GROUP X =================
            asm volatile("bar.sync 3, 512;" ::: "memory");   // Y done reading old slots (+Y STS visible)

            // STS refresh (rows 0-7 of the 16 tail rows) into recycled slots
            if (it >= 1 && it < CHAIN) {
                const int krow = tid >> 5;     // 0..7
                const int kcol = tid & 31;
                int slot = rotP + krow; if (slot >= ROWS) slot -= ROWS;
                float4* dst = tile4 + slot * PITCH4 + kcol;
                #pragma unroll
                for (int c = 0; c < 8; ++c)
                    dst[32 * c] = st[c];
            }
            asm volatile("bar.sync 1, 256;" ::: "memory");   // X STS drained before A reads

            if (it < CHAIN) {
                // ----- Phase A: warp = (d-group g2 of 256 dims, j-half) -----
                {
                    const int w    = tid >> 5;
                    const int lane = tid & 31;
                    const int g2   = w >> 1;          // 0..3
                    const int j0   = (w & 1) * 24;    // j half
                    const int a    = lane >> 3;
                    const int b    = lane & 7;
                    const int base = g2 * 64;         // f4 col start (256 dims)

                    int qs[4], fs[3];
                    #pragma unroll
                    for (int ii = 0; ii < 4; ++ii) {
                        int r = a + 4 * ii + rotI; if (r >= ROWS) r -= ROWS;
                        qs[ii] = r * PITCH4;
                    }
                    #pragma unroll
                    for (int jj = 0; jj < 3; ++jj) {
                        int r = j0 + b + 8 * jj + rotI; if (r >= ROWS) r -= ROWS;
                        fs[jj] = r * PITCH4;
                    }

                    u64 acc[4][3];
                    #pragma unroll
                    for (int ii = 0; ii < 4; ++ii)
                        #pragma unroll
                        for (int jj = 0; jj < 3; ++jj)
                            acc[ii][jj] = 0ull;

                    #pragma unroll 4
                    for (int step = 0; step < 64; ++step) {
                        const int col = base + step;
                        ulonglong2 q[4], f[3];
                        #pragma unroll
                        for (int ii = 0; ii < 4; ++ii)
                            q[ii] = tileU[qs[ii] + col];
                        #pragma unroll
                        for (int jj = 0; jj < 3; ++jj)
                            f[jj] = tileU[fs[jj] + col];
                        #pragma unroll
                        for (int ii = 0; ii < 4; ++ii)
                            #pragma unroll
                            for (int jj = 0; jj < 3; ++jj) {
                                fma2(acc[ii][jj], q[ii].x, f[jj].x);
                                fma2(acc[ii][jj], q[ii].y, f[jj].y);
                            }
                    }

                    float* myred = red + g2 * (S_TILE * COLS);
                    #pragma unroll
                    for (int ii = 0; ii < 4; ++ii)
                        #pragma unroll
                        for (int jj = 0; jj < 3; ++jj)
                            myred[(a + 4 * ii) * COLS + (j0 + b + 8 * jj)] =
                                sum2(acc[ii][jj]);
                }
                asm volatile("bar.sync 1, 256;" ::: "memory");   // red complete

                // ----- softmax (8 warps x 2 rows) -> weight buffer bufC -----
                {
                    const int wq   = tid >> 5;
                    const int lane = tid & 31;
                    const int s0I  = (t0 + it) * S_TILE;
                    float2* Wc2 = reinterpret_cast<float2*>(Wd + bufC * W_U64);
                    #pragma unroll
                    for (int rr = 0; rr < 2; ++rr) {
                        const int row = wq * 2 + rr;
                        float s1 = 0.0f, s2 = 0.0f;
                        #pragma unroll
                        for (int g = 0; g < 4; ++g)
                            s1 += red[g * (S_TILE * COLS) + row * COLS + lane];
                        if (lane < 16) {
                            #pragma unroll
                            for (int g = 0; g < 4; ++g)
                                s2 += red[g * (S_TILE * COLS) + row * COLS + 32 + lane];
                        }

                        const int j1 = lane;
                        const int k1 = j1 - row - 1;
                        const bool val1 = (k1 >= 0) && (k1 < KF) && (s0I + j1 < S);
                        const float v1 = val1 ? s1 : NEG_BIG;

                        const int j2 = 32 + lane;
                        const int k2 = j2 - row - 1;
                        const bool val2 = (lane < 16) && (k2 >= 0) && (k2 < KF) && (s0I + j2 < S);
                        const float v2 = val2 ? s2 : NEG_BIG;

                        float m = fmaxf(v1, v2);
                        #pragma unroll
                        for (int o = 16; o > 0; o >>= 1)
                            m = fmaxf(m, __shfl_xor_sync(0xFFFFFFFFu, m, o));

                        const float e1 = __expf(v1 - m);
                        const float e2 = (lane < 16) ? __expf(v2 - m) : 0.0f;
                        float sum = e1 + e2;
                        #pragma unroll
                        for (int o = 16; o > 0; o >>= 1)
                            sum += __shfl_xor_sync(0xFFFFFFFFu, sum, o);
                        const float inv = 1.0f / sum;

                        const int wbase = WROW(row);
                        const float w1 = val1 ? e1 * inv : 0.0f;
                        Wc2[wbase + j1] = make_float2(w1, w1);
                        if (lane < 16) {
                            const float w2 = val2 ? e2 * inv : 0.0f;
                            Wc2[wbase + j2] = make_float2(w2, w2);
                        }
                    }
                }
            }
        } else {
            // ================= GROUP Y =================
            const int wy   = (tid >> 5) - 8;   // 0..7
            const int lane = tid & 31;
            const int b    = wy * 32 + lane;   // f4 column 0..255
            const u64* Wp  = Wd + bufP * W_U64;

            u64 acc[16][2];
            #pragma unroll
            for (int ii = 0; ii < 16; ++ii) { acc[ii][0] = 0ull; acc[ii][1] = 0ull; }

            if (it >= 1) {
                // B(it-1): first 8 j-pairs = j 0..15 (the slots about to die)
                #pragma unroll 2
                for (int jp = 0; jp < 8; ++jp) {
                    const int jl = jp * 2;
                    int sl1 = jl + rotP;     if (sl1 >= ROWS) sl1 -= ROWS;
                    int sl2 = jl + 1 + rotP; if (sl2 >= ROWS) sl2 -= ROWS;
                    const ulonglong2 f1 = tileU[sl1 * PITCH4 + b];
                    const ulonglong2 f2 = tileU[sl2 * PITCH4 + b];
                    #pragma unroll
                    for (int ii = 0; ii < 16; ++ii) {
                        const ulonglong2 wp =
                            *reinterpret_cast<const ulonglong2*>(&Wp[WROW(ii) + jl]);
                        fma2(acc[ii][0], wp.x, f1.x);
                        fma2(acc[ii][1], wp.x, f1.y);
                        fma2(acc[ii][0], wp.y, f2.x);
                        fma2(acc[ii][1], wp.y, f2.y);
                    }
                }
            }

            asm volatile("bar.sync 2, 256;" ::: "memory");   // all Y done reading old slots

            // STS refresh (rows 8-15) into recycled slots
            if (it >= 1 && it < CHAIN) {
                const int krow = tid >> 5;     // 8..15
                const int kcol = tid & 31;
                int slot = rotP + krow; if (slot >= ROWS) slot -= ROWS;
                float4* dst = tile4 + slot * PITCH4 + kcol;
                #pragma unroll
                for (int c = 0; c < 8; ++c)
                    dst[32 * c] = st[c];
            }
            asm volatile("bar.arrive 3, 512;" ::: "memory"); // release X

            if (it >= 1) {
                // B(it-1): remaining 16 j-pairs
                #pragma unroll 2
                for (int jp = 8; jp < 24; ++jp) {
                    const int jl = jp * 2;
                    int sl1 = jl + rotP;     if (sl1 >= ROWS) sl1 -= ROWS;
                    int sl2 = jl + 1 + rotP; if (sl2 >= ROWS) sl2 -= ROWS;
                    const ulonglong2 f1 = tileU[sl1 * PITCH4 + b];
                    const ulonglong2 f2 = tileU[sl2 * PITCH4 + b];
                    #pragma unroll
                    for (int ii = 0; ii < 16; ++ii) {
                        const ulonglong2 wp =
                            *reinterpret_cast<const ulonglong2*>(&Wp[WROW(ii) + jl]);
                        fma2(acc[ii][0], wp.x, f1.x);
                        fma2(acc[ii][1], wp.x, f1.y);
                        fma2(acc[ii][0], wp.y, f2.x);
                        fma2(acc[ii][1], wp.y, f2.y);
                    }
                }

                const int s0B = (t0 + it - 1) * S_TILE;
                #pragma unroll
                for (int ii = 0; ii < 16; ++ii) {
                    const int s = s0B + ii;
                    if (s < S) {
                        const float2 lo = *reinterpret_cast<float2*>(&acc[ii][0]);
                        const float2 hi = *reinterpret_cast<float2*>(&acc[ii][1]);
                        out4[(size_t)s * D4 + b] = make_float4(lo.x, lo.y, hi.x, hi.y);
                    }
                }
            }
        }

        // ---- stash LDG for tile it+1's tail rows (all 512 threads) ----
        if (it < CHAIN - 1) {
            const int krow = tid >> 5;     // 0..15
            const int kcol = tid & 31;
            int gr = t0 * S_TILE + it * S_TILE + ROWS + krow;
            if (gr > S - 1) gr = S - 1;
            const float4* src = in4 + (size_t)gr * D4 + kcol;
            #pragma unroll
            for (int c = 0; c < 8; ++c)
                st[c] = src[32 * c];
        }
    }
}

extern "C" void kernel_launch(void* const* d_in, const int* in_sizes, int n_in,
                              void* d_out, int out_size)
{
    (void)n_in; (void)out_size;
    const float* in = (const float*)d_in[0];
    float* out = (float*)d_out;

    const int S = 2048;
    const int B = in_sizes[0] / (S * DCONST);
    const int chains = S / (S_TILE * CHAIN);   // 32

    cudaFuncSetAttribute(future_encoder_kernel,
                         cudaFuncAttributeMaxDynamicSharedMemorySize,
                         SMEM_BYTES);

    dim3 grid(chains, B);
    future_encoder_kernel<<<grid, 512, SMEM_BYTES>>>(in, out, S);
}